// round 4
// baseline (speedup 1.0000x reference)
#include <cuda_runtime.h>
#include <math.h>

#define MAXSEG1 257
#define TRCAP   512
#define LUTN    4096
#define NBLK    148
#define NTHR    256

// ---------------- device scratch (zero-initialized at load) ----------------
__device__ float2   d_RS[TRCAP * 256];   // {R,S} per refined seg per dim
__device__ float    d_binW[TRCAP];
__device__ float    d_binWE[TRCAP];
__device__ unsigned g_done;              // monotonic completion ticket

__global__ __launch_bounds__(NTHR, 1)
void k_fused(const float* __restrict__ adj, int P,
             const float* __restrict__ W1a, const float* __restrict__ b1a,
             const float* __restrict__ W1b, const float* __restrict__ b1b,
             const float* __restrict__ W2a, const float* __restrict__ b2a,
             const float* __restrict__ W2b, const float* __restrict__ b2b,
             const float* __restrict__ W3a, const float* __restrict__ b3a,
             const float* __restrict__ W3b, const float* __restrict__ b3b,
             const float* __restrict__ W4a, const float* __restrict__ b4a,
             const float* __restrict__ W4b, const float* __restrict__ b4b,
             float* __restrict__ out)
{
    __shared__ float s_W1a[256], s_B1a[256];
    __shared__ float s_t[MAXSEG1 + 1];
    __shared__ float s_C[128], s_D[128];
    __shared__ float s_u[128], s_v[128], s_w2b[128];
    __shared__ float s_r[256], s_s[256];
    __shared__ float s_sort[TRCAP];
    __shared__ float s_tr[TRCAP + 1];
    __shared__ float2 s_AB[TRCAP];
    __shared__ unsigned short s_lut[LUTN];
    __shared__ float s_W[TRCAP], s_WE[TRCAP];
    __shared__ float s_red[NTHR];
    __shared__ int s_cnt, s_nseg, s_rcnt, s_total;
    __shared__ unsigned s_tk;

    int tid = threadIdx.x, bid = blockIdx.x;

    // ---------- P0: layer-1 breakpoints in (0,1), sorted (redundant/block) ----------
    s_W1a[tid] = W1a[tid];
    s_B1a[tid] = b1a[tid];
    if (tid == 0) s_cnt = 0;
    __syncthreads();
    {
        float a = s_W1a[tid], b = s_B1a[tid];
        if (a != 0.0f) {
            float t = -b / a;
            if (t > 0.0f && t < 1.0f) s_sort[atomicAdd(&s_cnt, 1)] = t;
        }
    }
    __syncthreads();
    int n0 = s_cnt;
    if (tid >= n0) s_sort[tid] = 2.0f;
    __syncthreads();
    for (int k = 2; k <= 256; k <<= 1)
        for (int j = k >> 1; j > 0; j >>= 1) {
            int ixj = tid ^ j;
            if (ixj > tid) {
                float x = s_sort[tid], y = s_sort[ixj];
                bool up = ((tid & k) == 0);
                if ((x > y) == up) { s_sort[tid] = y; s_sort[ixj] = x; }
            }
            __syncthreads();
        }
    if (tid < n0) s_t[tid + 1] = s_sort[tid];
    if (tid == 0) { s_t[0] = 0.0f; s_t[n0 + 1] = 1.0f; s_nseg = n0 + 1; s_total = 0; }
    __syncthreads();
    int nseg1 = s_nseg;
    float b2bv = __ldg(b2b);
    float gm = -3.0e38f;

    // ---------- P1..P3: per L1 seg: linearize, refine, AB table, RS rows ----------
    for (int seg1 = 0; seg1 < nseg1; seg1++) {
        float lo1 = s_t[seg1], hi1 = s_t[seg1 + 1];
        float em1 = 0.5f * (lo1 + hi1);
        if (tid < 128) {
            float c = 0.0f, dd = 0.0f;
            #pragma unroll 4
            for (int j = 0; j < 256; j++) {
                float a = s_W1a[j], b = s_B1a[j];
                if (fmaf(a, em1, b) > 0.0f) {
                    float w = __ldg(W1b + j * 128 + tid);
                    c = fmaf(a, w, c); dd = fmaf(b, w, dd);
                }
            }
            s_C[tid] = c; s_D[tid] = dd + __ldg(b1b + tid);
        }
        __syncthreads();
        if (tid < 128) {
            float uu = 0.0f, vv = __ldg(b2a + tid);
            #pragma unroll 4
            for (int k = 0; k < 128; k++) {
                float w = __ldg(W2a + k * 128 + tid);
                uu = fmaf(s_C[k], w, uu); vv = fmaf(s_D[k], w, vv);
            }
            s_u[tid] = uu; s_v[tid] = vv; s_w2b[tid] = __ldg(W2b + tid);
        }
        {
            float r = 0.0f, sv = __ldg(b3a + tid);
            #pragma unroll 4
            for (int k = 0; k < 128; k++) {
                float w = __ldg(W3a + k * 256 + tid);
                r = fmaf(s_C[k], w, r); sv = fmaf(s_D[k], w, sv);
            }
            s_r[tid] = r; s_s[tid] = sv;
        }
        if (tid == 0) s_rcnt = 0;
        __syncthreads();
        // collect layer-2 roots inside (lo1, hi1)
        if (tid < 128) {
            float a = s_u[tid], b = s_v[tid];
            if (a != 0.0f) {
                float t = -b / a;
                if (t > lo1 && t < hi1) { int p = atomicAdd(&s_rcnt, 1); if (p < TRCAP) s_sort[p] = t; }
            }
        }
        {
            float a = s_r[tid], b = s_s[tid];
            if (a != 0.0f) {
                float t = -b / a;
                if (t > lo1 && t < hi1) { int p = atomicAdd(&s_rcnt, 1); if (p < TRCAP) s_sort[p] = t; }
            }
        }
        __syncthreads();
        int m0 = min(s_rcnt, TRCAP - 1);
        for (int i = m0 + tid; i < TRCAP; i += NTHR) s_sort[i] = 2.0f;
        __syncthreads();
        // bitonic sort TRCAP wide, 2 elems/thread
        for (int k = 2; k <= TRCAP; k <<= 1)
            for (int j = k >> 1; j > 0; j >>= 1) {
                for (int i = tid; i < TRCAP; i += NTHR) {
                    int ixj = i ^ j;
                    if (ixj > i) {
                        float x = s_sort[i], y = s_sort[ixj];
                        bool up = ((i & k) == 0);
                        if ((x > y) == up) { s_sort[i] = y; s_sort[ixj] = x; }
                    }
                }
                __syncthreads();
            }
        int base = s_total;
        int subcnt = m0 + 1;
        if (base + subcnt > TRCAP) subcnt = TRCAP - base;   // safety clamp
        if (subcnt <= 0) { __syncthreads(); continue; }
        if (tid == 0) s_tr[base] = lo1;
        for (int i = tid; i < subcnt - 1; i += NTHR) s_tr[base + 1 + i] = s_sort[i];
        __syncthreads();
        // logit affine {A,B} per sub-seg + domain max for softmax shift
        for (int js = tid; js < subcnt; js += NTHR) {
            float slo = s_tr[base + js];
            float shi = (js == subcnt - 1) ? hi1 : s_tr[base + js + 1];
            float em = 0.5f * (slo + shi);
            float A = 0.0f, B = 0.0f;
            #pragma unroll 4
            for (int i = 0; i < 128; i++) {
                if (fmaf(s_u[i], em, s_v[i]) > 0.0f) { A += s_u[i] * s_w2b[i]; B += s_v[i] * s_w2b[i]; }
            }
            B += b2bv;
            s_AB[base + js] = make_float2(A, B);
            gm = fmaxf(gm, fmaxf(fmaf(A, slo, B), fmaf(A, shi, B)));
        }
        // distributed RS rows (value path, masked by activation at midpoint)
        for (int js = 0; js < subcnt; js++) {
            int gs = base + js;
            if ((gs % NBLK) == bid) {
                float slo = s_tr[gs];
                float shi = (js == subcnt - 1) ? hi1 : s_tr[gs + 1];
                float em = 0.5f * (slo + shi);
                bool act = fmaf(s_r[tid], em, s_s[tid]) > 0.0f;
                d_RS[gs * 256 + tid] = make_float2(act ? s_r[tid] : 0.0f,
                                                   act ? s_s[tid] : 0.0f);
            }
        }
        if (tid == 0) s_total = base + subcnt;
        __syncthreads();
    }
    int nref = s_total;
    if (tid == 0) s_tr[nref] = 1.0f;
    // gmax reduce (identical in every block)
    s_red[tid] = gm;
    __syncthreads();
    for (int s = 128; s > 0; s >>= 1) {
        if (tid < s) s_red[tid] = fmaxf(s_red[tid], s_red[tid + s]);
        __syncthreads();
    }
    float gmax = s_red[0];
    // LUT over [0,1)
    for (int b = tid; b < LUTN; b += NTHR) {
        float e = (float)b * (1.0f / LUTN);
        int lo = 0, hi = nref - 1;
        while (lo < hi) { int mid = (lo + hi + 1) >> 1; if (s_tr[mid] <= e) lo = mid; else hi = mid - 1; }
        s_lut[b] = (unsigned short)lo;
    }
    for (int i = tid; i < nref; i += NTHR) { s_W[i] = 0.0f; s_WE[i] = 0.0f; }
    __syncthreads();

    // ---------- P4: edge pass, O(1)/edge, all-shared tables ----------
    {
        int nq = P >> 2;
        const float4* a4 = (const float4*)adj;
        for (int q = bid * NTHR + tid; q < nq; q += NBLK * NTHR) {
            float4 v = __ldg(a4 + q);
            float es[4] = {v.x, v.y, v.z, v.w};
            #pragma unroll
            for (int j = 0; j < 4; j++) {
                float e = es[j];
                if (e > 0.0f && e < 1.0f) {
                    int b = min((int)(e * (float)LUTN), LUTN - 1);
                    int seg = s_lut[b];
                    while (seg + 1 < nref && e >= s_tr[seg + 1]) seg++;
                    float2 ab = s_AB[seg];
                    float w = __expf(fmaf(ab.x, e, ab.y) - gmax);
                    atomicAdd(&s_W[seg], w);
                    atomicAdd(&s_WE[seg], w * e);
                }
            }
        }
        for (int p = (nq << 2) + bid * NTHR + tid; p < P; p += NBLK * NTHR) {
            float e = __ldg(adj + p);
            if (e > 0.0f && e < 1.0f) {
                int b = min((int)(e * (float)LUTN), LUTN - 1);
                int seg = s_lut[b];
                while (seg + 1 < nref && e >= s_tr[seg + 1]) seg++;
                float2 ab = s_AB[seg];
                float w = __expf(fmaf(ab.x, e, ab.y) - gmax);
                atomicAdd(&s_W[seg], w);
                atomicAdd(&s_WE[seg], w * e);
            }
        }
        __syncthreads();
        for (int i = tid; i < nref; i += NTHR) {
            float w = s_W[i], we = s_WE[i];
            if (w != 0.0f || we != 0.0f) {
                atomicAdd(&d_binW[i], w);
                atomicAdd(&d_binWE[i], we);
            }
        }
    }

    // ---------- completion signal (no mutual barrier; only block 0 waits) ----------
    __syncthreads();
    if (tid == 0) {
        __threadfence();
        s_tk = atomicAdd(&g_done, 1u);
    }
    __syncthreads();
    if (bid != 0) return;          // all other blocks retire immediately
    if (tid == 0) {
        unsigned target = (s_tk / NBLK + 1u) * NBLK;   // end of this run's ticket range
        for (;;) {
            unsigned cur;
            asm volatile("ld.volatile.global.u32 %0, [%1];" : "=r"(cur) : "l"(&g_done));
            if ((int)(cur - target) >= 0) break;
            __nanosleep(64);
        }
        __threadfence();
    }
    __syncthreads();

    // ---------- P5 (block 0): combine bins -> H, W3b, fc4 head; reset bins ----------
    for (int i = tid; i < nref; i += NTHR) { s_W[i] = d_binW[i]; s_WE[i] = d_binWE[i]; }
    __syncthreads();
    float acc = 0.0f;
    for (int rs = 0; rs < nref; rs++) {
        float w = s_W[rs], we = s_WE[rs];
        if (w == 0.0f && we == 0.0f) continue;          // uniform branch
        float2 rsv = __ldg(&d_RS[rs * 256 + tid]);
        acc = fmaf(we, rsv.x, fmaf(w, rsv.y, acc));
    }
    float z = 0.0f;
    for (int i = tid; i < nref; i += NTHR) z += s_W[i];
    s_red[tid] = z;
    __syncthreads();
    for (int s = 128; s > 0; s >>= 1) {
        if (tid < s) s_red[tid] += s_red[tid + s];
        __syncthreads();
    }
    float Z = s_red[0];
    float invZ = (Z > 0.0f) ? (1.0f / Z) : 0.0f;
    float S0   = (Z > 0.0f) ? 1.0f : 0.0f;
    __syncthreads();
    s_r[tid] = acc * invZ;          // Hn[256]
    __syncthreads();
    if (tid < 128) {                // weighted = Hn @ W3b + b3b
        float a2 = S0 * __ldg(b3b + tid);
        #pragma unroll 4
        for (int d = 0; d < 256; d++)
            a2 = fmaf(s_r[d], __ldg(W3b + d * 128 + tid), a2);
        s_C[tid] = a2;
    }
    __syncthreads();
    {                               // h4 = relu(weighted @ W4a + b4a)
        float a3 = __ldg(b4a + tid);
        #pragma unroll 4
        for (int m = 0; m < 128; m++)
            a3 = fmaf(s_C[m], __ldg(W4a + m * 256 + tid), a3);
        s_s[tid] = fmaxf(a3, 0.0f);
    }
    __syncthreads();
    if (tid < 64) {                 // out = h4 @ W4b + b4b
        float a4v = __ldg(b4b + tid);
        #pragma unroll 4
        for (int n = 0; n < 256; n++)
            a4v = fmaf(s_s[n], __ldg(W4b + n * 64 + tid), a4v);
        out[tid] = a4v;
    }
    for (int i = tid; i < nref; i += NTHR) { d_binW[i] = 0.0f; d_binWE[i] = 0.0f; }
}

// ---------------- launch: ONE kernel, one graph node ----------------
extern "C" void kernel_launch(void* const* d_in, const int* in_sizes, int n_in,
                              void* d_out, int out_size) {
    const float* adj = (const float*)d_in[1];
    int P = in_sizes[1];
    k_fused<<<NBLK, NTHR>>>(adj, P,
        (const float*)d_in[3],  (const float*)d_in[4],
        (const float*)d_in[5],  (const float*)d_in[6],
        (const float*)d_in[7],  (const float*)d_in[8],
        (const float*)d_in[9],  (const float*)d_in[10],
        (const float*)d_in[11], (const float*)d_in[12],
        (const float*)d_in[13], (const float*)d_in[14],
        (const float*)d_in[15], (const float*)d_in[16],
        (const float*)d_in[17], (const float*)d_in[18],
        (float*)d_out);
}

// round 6
// speedup vs baseline: 1.7709x; 1.7709x over previous
#include <cuda_runtime.h>
#include <math.h>

#define MAXSEG1 257
#define TRCAP   512
#define LUTN    4096
#define NBLK    148
#define NTHR    512

// ---------------- device scratch (zero-initialized at load) ----------------
__device__ float    d_H[257];     // [0..255]=H accum, [256]=Z accum
__device__ unsigned g_done;       // monotonic completion ticket
__device__ float    d_sink;

// Linearize the 1-D input network on one L1 segment (midpoint em1):
// emb(e)=e*C+D; logit pre-act (u,v); value pre-act (r,s). Full-block collective.
__device__ __forceinline__ void linearize(
    float em1, int tid, int col, int team, int col2, int team2,
    const float* s_W1a, const float* s_B1a,
    const float* __restrict__ W1b, const float* __restrict__ b1b,
    const float* __restrict__ W2a, const float* __restrict__ b2a,
    const float* __restrict__ W2b,
    const float* __restrict__ W3a, const float* __restrict__ b3a,
    float (*s_pa)[128], float (*s_pb)[128],
    float* s_C, float* s_D, float* s_u, float* s_v, float* s_w2b,
    float (*s_pr)[256], float (*s_ps)[256],
    float* s_r, float* s_s, bool need_logit)
{
    // ---- C/D: 4 teams x 64 j's, cols 0..127 ----
    {
        float c = 0.0f, d = 0.0f;
        int j0 = team * 64;
        #pragma unroll 16
        for (int j = j0; j < j0 + 64; j++) {
            float a = s_W1a[j], b = s_B1a[j];
            float w = __ldg(W1b + j * 128 + col);
            if (fmaf(a, em1, b) > 0.0f) { c = fmaf(a, w, c); d = fmaf(b, w, d); }
        }
        s_pa[team][col] = c; s_pb[team][col] = d;
    }
    __syncthreads();
    if (tid < 128) {
        s_C[tid] = s_pa[0][tid] + s_pa[1][tid] + s_pa[2][tid] + s_pa[3][tid];
        s_D[tid] = s_pb[0][tid] + s_pb[1][tid] + s_pb[2][tid] + s_pb[3][tid] + __ldg(b1b + tid);
    }
    __syncthreads();
    // ---- u/v (logit path): 4 teams x 32 k's ----
    if (need_logit) {
        float uu = 0.0f, vv = 0.0f;
        int k0 = team * 32;
        #pragma unroll
        for (int k = k0; k < k0 + 32; k++) {
            float w = __ldg(W2a + k * 128 + col);
            uu = fmaf(s_C[k], w, uu); vv = fmaf(s_D[k], w, vv);
        }
        s_pa[team][col] = uu; s_pb[team][col] = vv;
        __syncthreads();
        if (tid < 128) {
            s_u[tid] = s_pa[0][tid] + s_pa[1][tid] + s_pa[2][tid] + s_pa[3][tid];
            s_v[tid] = s_pb[0][tid] + s_pb[1][tid] + s_pb[2][tid] + s_pb[3][tid] + __ldg(b2a + tid);
            s_w2b[tid] = __ldg(W2b + tid);
        }
    }
    // ---- r/s (value path): 2 teams x 64 k's, cols 0..255 ----
    {
        float r = 0.0f, sv = 0.0f;
        int k0 = team2 * 64;
        #pragma unroll 8
        for (int k = k0; k < k0 + 64; k++) {
            float w = __ldg(W3a + k * 256 + col2);
            r = fmaf(s_C[k], w, r); sv = fmaf(s_D[k], w, sv);
        }
        s_pr[team2][col2] = r; s_ps[team2][col2] = sv;
    }
    __syncthreads();
    if (tid < 256) {
        s_r[tid] = s_pr[0][tid] + s_pr[1][tid];
        s_s[tid] = s_ps[0][tid] + s_ps[1][tid] + __ldg(b3a + tid);
    }
    __syncthreads();
}

__global__ __launch_bounds__(NTHR, 1)
void k_fused(const float* __restrict__ adj, int P,
             const float* __restrict__ W1a, const float* __restrict__ b1a,
             const float* __restrict__ W1b, const float* __restrict__ b1b,
             const float* __restrict__ W2a, const float* __restrict__ b2a,
             const float* __restrict__ W2b, const float* __restrict__ b2b,
             const float* __restrict__ W3a, const float* __restrict__ b3a,
             const float* __restrict__ W3b, const float* __restrict__ b3b,
             const float* __restrict__ W4a, const float* __restrict__ b4a,
             const float* __restrict__ W4b, const float* __restrict__ b4b,
             float* __restrict__ out)
{
    __shared__ float s_W1a[256], s_B1a[256];
    __shared__ float s_t[MAXSEG1 + 1];
    __shared__ int   s_pstart[MAXSEG1 + 1];
    __shared__ float s_pa[4][128], s_pb[4][128];
    __shared__ float s_C[128], s_D[128];
    __shared__ float s_u[128], s_v[128], s_w2b[128];
    __shared__ float s_pr[2][256], s_ps[2][256];
    __shared__ float s_r[256], s_s[256];
    __shared__ float s_sort[TRCAP];
    __shared__ float s_tr[TRCAP + 1];
    __shared__ float2 s_AB[TRCAP];
    __shared__ unsigned short s_lut[LUTN];
    __shared__ float s_W[TRCAP], s_WE[TRCAP];
    __shared__ float s_red[NTHR];
    __shared__ float s_Hn[256], s_Wt[128], s_H4[256];
    __shared__ int s_cnt, s_nseg, s_rcnt, s_total;
    __shared__ unsigned s_tk;
    __shared__ float s_Z;

    int tid = threadIdx.x, bid = blockIdx.x;
    int col = tid & 127, team = tid >> 7;     // 4 teams of 128
    int col2 = tid & 255, team2 = tid >> 8;   // 2 teams of 256

    // ---------- P0: layer-1 breakpoints in (0,1) ----------
    if (tid < 256) { s_W1a[tid] = W1a[tid]; s_B1a[tid] = b1a[tid]; }
    if (tid == 0) { s_cnt = 0; s_total = 0; }
    __syncthreads();
    if (tid < 256) {
        float a = s_W1a[tid], b = s_B1a[tid];
        if (a != 0.0f) {
            float t = -b / a;
            if (t > 0.0f && t < 1.0f) s_sort[atomicAdd(&s_cnt, 1)] = t;
        }
    }
    __syncthreads();
    int n0 = s_cnt;
    if (n0 > 1) {   // sort only when needed
        if (tid < 256 && tid >= n0) s_sort[tid] = 2.0f;
        __syncthreads();
        for (int k = 2; k <= 256; k <<= 1)
            for (int j = k >> 1; j > 0; j >>= 1) {
                if (tid < 256) {
                    int ixj = tid ^ j;
                    if (ixj > tid) {
                        float x = s_sort[tid], y = s_sort[ixj];
                        bool up = ((tid & k) == 0);
                        if ((x > y) == up) { s_sort[tid] = y; s_sort[ixj] = x; }
                    }
                }
                __syncthreads();
            }
    }
    if (tid < n0) s_t[tid + 1] = s_sort[tid];
    if (tid == 0) { s_t[0] = 0.0f; s_t[n0 + 1] = 1.0f; s_nseg = n0 + 1; }
    __syncthreads();
    int nseg1 = s_nseg;
    float b2bv = __ldg(b2b);
    float gm = -3.0e38f;

    // ---------- setup: per L1 parent: linearize, refine, AB table ----------
    for (int p = 0; p < nseg1; p++) {
        float lo1 = s_t[p], hi1 = s_t[p + 1];
        linearize(0.5f * (lo1 + hi1), tid, col, team, col2, team2,
                  s_W1a, s_B1a, W1b, b1b, W2a, b2a, W2b, W3a, b3a,
                  s_pa, s_pb, s_C, s_D, s_u, s_v, s_w2b, s_pr, s_ps, s_r, s_s, true);
        if (tid == 0) s_rcnt = 0;
        __syncthreads();
        if (tid < 128) {
            float a = s_u[tid], b = s_v[tid];
            if (a != 0.0f) {
                float t = -b / a;
                if (t > lo1 && t < hi1) { int q = atomicAdd(&s_rcnt, 1); if (q < TRCAP) s_sort[q] = t; }
            }
        }
        if (tid < 256) {
            float a = s_r[tid], b = s_s[tid];
            if (a != 0.0f) {
                float t = -b / a;
                if (t > lo1 && t < hi1) { int q = atomicAdd(&s_rcnt, 1); if (q < TRCAP) s_sort[q] = t; }
            }
        }
        __syncthreads();
        int m0 = min(s_rcnt, TRCAP - 1);
        if (tid >= m0) s_sort[tid] = 2.0f;     // NTHR == TRCAP
        __syncthreads();
        for (int k = 2; k <= TRCAP; k <<= 1)
            for (int j = k >> 1; j > 0; j >>= 1) {
                int ixj = tid ^ j;
                if (ixj > tid) {
                    float x = s_sort[tid], y = s_sort[ixj];
                    bool up = ((tid & k) == 0);
                    if ((x > y) == up) { s_sort[tid] = y; s_sort[ixj] = x; }
                }
                __syncthreads();
            }
        int base = s_total;
        int subcnt = m0 + 1;
        if (base + subcnt > TRCAP) subcnt = TRCAP - base;
        if (tid == 0) s_pstart[p] = base;
        if (subcnt > 0) {
            if (tid == 0) s_tr[base] = lo1;
            for (int i = tid; i < subcnt - 1; i += NTHR) s_tr[base + 1 + i] = s_sort[i];
            __syncthreads();
            for (int js = tid; js < subcnt; js += NTHR) {
                float slo = s_tr[base + js];
                float shi = (js == subcnt - 1) ? hi1 : s_tr[base + js + 1];
                float em = 0.5f * (slo + shi);
                float A = 0.0f, Bv = 0.0f;
                #pragma unroll 4
                for (int i = 0; i < 128; i++)
                    if (fmaf(s_u[i], em, s_v[i]) > 0.0f) { A += s_u[i] * s_w2b[i]; Bv += s_v[i] * s_w2b[i]; }
                Bv += b2bv;
                s_AB[base + js] = make_float2(A, Bv);
                gm = fmaxf(gm, fmaxf(fmaf(A, slo, Bv), fmaf(A, shi, Bv)));
            }
            if (tid == 0) s_total = base + subcnt;
        }
        __syncthreads();
    }
    int nref = s_total;
    if (tid == 0) { s_tr[nref] = 1.0f; s_pstart[nseg1] = nref; }
    // gmax reduce (identical every block)
    s_red[tid] = gm;
    __syncthreads();
    for (int s = 256; s > 0; s >>= 1) {
        if (tid < s) s_red[tid] = fmaxf(s_red[tid], s_red[tid + s]);
        __syncthreads();
    }
    float gmax = s_red[0];
    // LUT
    for (int b = tid; b < LUTN; b += NTHR) {
        float e = (float)b * (1.0f / LUTN);
        int lo = 0, hi = nref - 1;
        while (lo < hi) { int mid = (lo + hi + 1) >> 1; if (s_tr[mid] <= e) lo = mid; else hi = mid - 1; }
        s_lut[b] = (unsigned short)lo;
    }
    for (int i = tid; i < nref; i += NTHR) { s_W[i] = 0.0f; s_WE[i] = 0.0f; }
    __syncthreads();

    // ---------- edge pass: O(1)/edge into block-local shared bins ----------
    {
        int nq = P >> 2;
        const float4* a4 = (const float4*)adj;
        for (int q = bid * NTHR + tid; q < nq; q += NBLK * NTHR) {
            float4 v = __ldg(a4 + q);
            float es[4] = {v.x, v.y, v.z, v.w};
            #pragma unroll
            for (int j = 0; j < 4; j++) {
                float e = es[j];
                if (e > 0.0f && e < 1.0f) {
                    int b = min((int)(e * (float)LUTN), LUTN - 1);
                    int seg = s_lut[b];
                    while (seg + 1 < nref && e >= s_tr[seg + 1]) seg++;
                    float2 ab = s_AB[seg];
                    float w = __expf(fmaf(ab.x, e, ab.y) - gmax);
                    atomicAdd(&s_W[seg], w);
                    atomicAdd(&s_WE[seg], w * e);
                }
            }
        }
        for (int pp = (nq << 2) + bid * NTHR + tid; pp < P; pp += NBLK * NTHR) {
            float e = __ldg(adj + pp);
            if (e > 0.0f && e < 1.0f) {
                int b = min((int)(e * (float)LUTN), LUTN - 1);
                int seg = s_lut[b];
                while (seg + 1 < nref && e >= s_tr[seg + 1]) seg++;
                float2 ab = s_AB[seg];
                float w = __expf(fmaf(ab.x, e, ab.y) - gmax);
                atomicAdd(&s_W[seg], w);
                atomicAdd(&s_WE[seg], w * e);
            }
        }
    }
    __syncthreads();

    // ---------- local combine: H_partial[d] = sum_seg WE*R + W*S (ALU-only) ----------
    float accH = 0.0f;
    for (int p = nseg1 - 1; p >= 0; p--) {
        if (p != nseg1 - 1)   // s_r/s_s already hold the LAST parent's values
            linearize(0.5f * (s_t[p] + s_t[p + 1]), tid, col, team, col2, team2,
                      s_W1a, s_B1a, W1b, b1b, W2a, b2a, W2b, W3a, b3a,
                      s_pa, s_pb, s_C, s_D, s_u, s_v, s_w2b, s_pr, s_ps, s_r, s_s, false);
        int rs0 = s_pstart[p], rs1 = s_pstart[p + 1];
        float rr = s_r[col2], ss = s_s[col2];
        for (int rs = rs0 + team2; rs < rs1; rs += 2) {
            float w = s_W[rs], we = s_WE[rs];
            float em = 0.5f * (s_tr[rs] + s_tr[rs + 1]);
            if (fmaf(rr, em, ss) > 0.0f) accH = fmaf(we, rr, fmaf(w, ss, accH));
        }
    }
    __syncthreads();
    s_pr[team2][col2] = accH;
    // Z partial
    {
        float z = 0.0f;
        for (int i = tid; i < nref; i += NTHR) z += s_W[i];
        s_red[tid] = z;
    }
    __syncthreads();
    for (int s = 256; s > 0; s >>= 1) {
        if (tid < s) s_red[tid] += s_red[tid + s];
        __syncthreads();
    }
    if (tid < 256) atomicAdd(&d_H[tid], s_pr[0][tid] + s_pr[1][tid]);
    if (tid == 0) atomicAdd(&d_H[256], s_red[0]);
    __threadfence();
    __syncthreads();
    if (tid == 0) s_tk = atomicAdd(&g_done, 1u);
    __syncthreads();

    // ---------- non-zero blocks: optional L2 warm for the head, then exit ----------
    if (bid != 0) {
        if (bid <= 3) {
            const float* wp = (bid == 1) ? W3b : (bid == 2) ? W4a : W4b;
            int n = (bid == 3) ? 256 * 64 : 256 * 128;
            float acc = 0.0f;
            for (int i = tid * 32; i < n; i += NTHR * 32) acc += __ldg(wp + i);
            if (acc == 1.0e38f) d_sink = acc;   // never true; defeats DCE
        }
        return;
    }

    // ---------- block 0: wait for all tickets of this run ----------
    if (tid == 0) {
        unsigned target = (s_tk / NBLK + 1u) * NBLK;
        for (;;) {
            unsigned cur;
            asm volatile("ld.volatile.global.u32 %0, [%1];" : "=r"(cur) : "l"(&g_done));
            if ((int)(cur - target) >= 0) break;
            __nanosleep(64);
        }
        __threadfence();
        s_Z = d_H[256];
    }
    __syncthreads();
    if (tid < 256) s_Hn[tid] = d_H[tid];
    __syncthreads();
    float Z = s_Z;
    float invZ = (Z > 0.0f) ? (1.0f / Z) : 0.0f;
    float S0   = (Z > 0.0f) ? 1.0f : 0.0f;
    if (tid < 256) s_Hn[tid] *= invZ;
    __syncthreads();

    // weighted = Hn @ W3b + S0*b3b  (4 teams over d)
    {
        float a2 = 0.0f;
        int d0 = team * 64;
        #pragma unroll 8
        for (int d = d0; d < d0 + 64; d++)
            a2 = fmaf(s_Hn[d], __ldg(W3b + d * 128 + col), a2);
        s_pa[team][col] = a2;
    }
    __syncthreads();
    if (tid < 128)
        s_Wt[tid] = s_pa[0][tid] + s_pa[1][tid] + s_pa[2][tid] + s_pa[3][tid] + S0 * __ldg(b3b + tid);
    __syncthreads();
    // h4 = relu(weighted @ W4a + b4a)  (2 teams over m)
    {
        float a3 = 0.0f;
        int m0 = team2 * 64;
        #pragma unroll 8
        for (int m = m0; m < m0 + 64; m++)
            a3 = fmaf(s_Wt[m], __ldg(W4a + m * 256 + col2), a3);
        s_pr[team2][col2] = a3;
    }
    __syncthreads();
    if (tid < 256) s_H4[tid] = fmaxf(s_pr[0][tid] + s_pr[1][tid] + __ldg(b4a + tid), 0.0f);
    __syncthreads();
    // out = h4 @ W4b + b4b  (8 teams of 64 over n)
    {
        int colO = tid & 63, team3 = tid >> 6;
        float a4 = 0.0f;
        int n0_ = team3 * 32;
        #pragma unroll 8
        for (int n = n0_; n < n0_ + 32; n++)
            a4 = fmaf(s_H4[n], __ldg(W4b + n * 64 + colO), a4);
        s_red[tid] = a4;
    }
    __syncthreads();
    if (tid < 64) {
        float o = __ldg(b4b + tid);
        #pragma unroll
        for (int q = 0; q < 8; q++) o += s_red[q * 64 + tid];
        out[tid] = o;
    }
    // reset accumulators for the next replay
    if (tid < 257) d_H[tid] = 0.0f;
}

// ---------------- launch: ONE kernel, one graph node ----------------
extern "C" void kernel_launch(void* const* d_in, const int* in_sizes, int n_in,
                              void* d_out, int out_size) {
    const float* adj = (const float*)d_in[1];
    int P = in_sizes[1];
    k_fused<<<NBLK, NTHR>>>(adj, P,
        (const float*)d_in[3],  (const float*)d_in[4],
        (const float*)d_in[5],  (const float*)d_in[6],
        (const float*)d_in[7],  (const float*)d_in[8],
        (const float*)d_in[9],  (const float*)d_in[10],
        (const float*)d_in[11], (const float*)d_in[12],
        (const float*)d_in[13], (const float*)d_in[14],
        (const float*)d_in[15], (const float*)d_in[16],
        (const float*)d_in[17], (const float*)d_in[18],
        (float*)d_out);
}

// round 7
// speedup vs baseline: 1.7799x; 1.0051x over previous
#include <cuda_runtime.h>
#include <math.h>

#define LUTN 2048
#define NBLK 148
#define NTHR 512

#define BARW(id,n) asm volatile("bar.sync %0, %1;" :: "r"(id), "r"(n) : "memory")

// ---------------- device scratch (zero-initialized at load) ----------------
__device__ float    d_binW[257];
__device__ float    d_binWE[257];
__device__ unsigned g_done;       // monotonic completion ticket
__device__ float    d_sink;

__global__ __launch_bounds__(NTHR, 1)
void k_fused(const float* __restrict__ adj, int P,
             const float* __restrict__ W1a, const float* __restrict__ b1a,
             const float* __restrict__ W1b, const float* __restrict__ b1b,
             const float* __restrict__ W2a, const float* __restrict__ b2a,
             const float* __restrict__ W2b, const float* __restrict__ b2b,
             const float* __restrict__ W3a, const float* __restrict__ b3a,
             const float* __restrict__ W3b, const float* __restrict__ b3b,
             const float* __restrict__ W4a, const float* __restrict__ b4a,
             const float* __restrict__ W4b, const float* __restrict__ b4b,
             float* __restrict__ out)
{
    __shared__ float s_W1a[256], s_B1a[256];
    __shared__ float s_pa[4][128], s_pb[4][128];
    __shared__ float s_pr[2][256], s_ps[2][256];
    __shared__ float s_C[128], s_D[128];
    __shared__ float s_u[128], s_v[128], s_w2b[128];
    __shared__ float s_r[256], s_s[256];
    __shared__ float s_ukey[128];  __shared__ int s_uidx[128];
    __shared__ float s_tkey[256];  __shared__ int s_tidx[256];
    __shared__ float s_dA[128], s_dB[128];
    __shared__ float s_uA[129], s_uB[129];
    __shared__ int   s_pos[256];
    __shared__ unsigned s_lut[LUTN];
    __shared__ float s_binW[257], s_binWE[257];
    __shared__ float s_PF[257], s_PG[257];
    __shared__ float s_red[NTHR];
    __shared__ float s_Hn[256], s_Wt[128], s_H4[256];
    __shared__ unsigned s_tk;
    __shared__ float s_Zs;

    int tid = threadIdx.x, bid = blockIdx.x;
    int col = tid & 127, team = tid >> 7;     // 4 teams of 128
    int col2 = tid & 255, team2 = tid >> 8;   // 2 teams of 256

    // ---------- P1: linearize whole network on (0,1) at em=0.5 ----------
    if (tid < 256) { s_W1a[tid] = W1a[tid]; s_B1a[tid] = b1a[tid]; }
    __syncthreads();
    const float em1 = 0.5f;
    {   // C/D: 4 teams x 64 j
        float c = 0.0f, d = 0.0f;
        int j0 = team * 64;
        #pragma unroll 16
        for (int j = j0; j < j0 + 64; j++) {
            float a = s_W1a[j], b = s_B1a[j];
            float w = __ldg(W1b + j * 128 + col);
            if (fmaf(a, em1, b) > 0.0f) { c = fmaf(a, w, c); d = fmaf(b, w, d); }
        }
        s_pa[team][col] = c; s_pb[team][col] = d;
    }
    __syncthreads();
    if (tid < 128) {
        s_C[tid] = s_pa[0][tid] + s_pa[1][tid] + s_pa[2][tid] + s_pa[3][tid];
        s_D[tid] = s_pb[0][tid] + s_pb[1][tid] + s_pb[2][tid] + s_pb[3][tid] + __ldg(b1b + tid);
    }
    __syncthreads();
    {   // u/v: 4 teams x 32 k
        float uu = 0.0f, vv = 0.0f;
        int k0 = team * 32;
        #pragma unroll
        for (int k = k0; k < k0 + 32; k++) {
            float w = __ldg(W2a + k * 128 + col);
            uu = fmaf(s_C[k], w, uu); vv = fmaf(s_D[k], w, vv);
        }
        s_pa[team][col] = uu; s_pb[team][col] = vv;
    }
    {   // r/s: 2 teams x 64 k
        float r = 0.0f, sv = 0.0f;
        int k0 = team2 * 64;
        #pragma unroll 8
        for (int k = k0; k < k0 + 64; k++) {
            float w = __ldg(W3a + k * 256 + col2);
            r = fmaf(s_C[k], w, r); sv = fmaf(s_D[k], w, sv);
        }
        s_pr[team2][col2] = r; s_ps[team2][col2] = sv;
    }
    __syncthreads();
    if (tid < 128) {
        s_u[tid] = s_pa[0][tid] + s_pa[1][tid] + s_pa[2][tid] + s_pa[3][tid] + __ldg(b2a + tid);
        s_v[tid] = s_u[tid]; // placeholder overwritten below (avoid extra sync cost)
    }
    // careful: u gets b2a? No: v gets b2a. Redo correctly:
    __syncthreads();
    if (tid < 128) {
        s_u[tid] = s_pa[0][tid] + s_pa[1][tid] + s_pa[2][tid] + s_pa[3][tid];
        s_v[tid] = s_pb[0][tid] + s_pb[1][tid] + s_pb[2][tid] + s_pb[3][tid] + __ldg(b2a + tid);
        s_w2b[tid] = __ldg(W2b + tid);
    }
    if (tid < 256) {
        s_r[tid] = s_pr[0][tid] + s_pr[1][tid];
        s_s[tid] = s_ps[0][tid] + s_ps[1][tid] + __ldg(b3a + tid);
    }
    __syncthreads();
    float b2bv = __ldg(b2b);

    // ---------- P2: fixed-slot keys (deterministic across blocks) ----------
    if (tid < 128) {
        float uu = s_u[tid], vv = s_v[tid];
        float key = 2.0f;
        if (uu != 0.0f) {
            float t = -vv / uu;
            if (t > 0.0f && t < 1.0f) key = t;
        }
        s_ukey[tid] = key; s_uidx[tid] = tid;
    }
    if (tid < 256) {
        float r = s_r[tid], sv = s_s[tid];
        float key = 1.0f;
        if (r != 0.0f) key = fminf(fmaxf(-sv / r, 0.0f), 1.0f);
        s_tkey[tid] = key; s_tidx[tid] = tid;
    }
    __syncthreads();

    // ---------- P3: concurrent bitonic sorts ----------
    if (tid < 128) {                       // warps 0-3: sort u-roots
        for (int k = 2; k <= 128; k <<= 1)
            for (int j = k >> 1; j > 0; j >>= 1) {
                int ixj = tid ^ j;
                if (ixj > tid) {
                    float x = s_ukey[tid], y = s_ukey[ixj];
                    bool up = ((tid & k) == 0);
                    if ((x > y) == up) {
                        s_ukey[tid] = y; s_ukey[ixj] = x;
                        int t = s_uidx[tid]; s_uidx[tid] = s_uidx[ixj]; s_uidx[ixj] = t;
                    }
                }
                BARW(1, 128);
            }
    } else if (tid >= 256) {               // warps 8-15: sort taus
        int i = tid - 256;
        for (int k = 2; k <= 256; k <<= 1)
            for (int j = k >> 1; j > 0; j >>= 1) {
                int ixj = i ^ j;
                if (ixj > i) {
                    float x = s_tkey[i], y = s_tkey[ixj];
                    bool up = ((i & k) == 0);
                    if ((x > y) == up) {
                        s_tkey[i] = y; s_tkey[ixj] = x;
                        int t = s_tidx[i]; s_tidx[i] = s_tidx[ixj]; s_tidx[ixj] = t;
                    }
                }
                BARW(2, 256);
            }
    }
    __syncthreads();
    if (tid < 256) s_pos[s_tidx[tid]] = tid + 1;   // boundary index per dim

    // ---------- P4: initial logit state + flip deltas + scan ----------
    float em0 = 0.5f * fminf(s_ukey[0], 1.0f);
    if (tid < 128) {
        bool act = fmaf(s_u[tid], em0, s_v[tid]) > 0.0f;
        s_red[tid]       = act ? s_u[tid] * s_w2b[tid] : 0.0f;
        s_red[256 + tid] = act ? s_v[tid] * s_w2b[tid] : 0.0f;
        float key = s_ukey[tid], dA = 0.0f, dB = 0.0f;
        if (key < 1.0f) {
            int i = s_uidx[tid];
            float sg = (s_u[i] > 0.0f) ? 1.0f : -1.0f;
            dA = sg * s_u[i] * s_w2b[i];
            dB = sg * s_v[i] * s_w2b[i];
        }
        s_dA[tid] = dA; s_dB[tid] = dB;
    }
    __syncthreads();
    for (int st = 64; st > 0; st >>= 1) {          // A0/B0 reduce
        if (tid < st) s_red[tid] += s_red[tid + st];
        else if (tid >= 256 && tid < 256 + st) s_red[tid] += s_red[tid + st];
        __syncthreads();
    }
    float A0 = s_red[0], B0 = s_red[256] + b2bv;
    __syncthreads();
    for (int off = 1; off < 128; off <<= 1) {      // inclusive scan of deltas
        float ta = 0.0f, tb = 0.0f;
        if (tid < 128 && tid >= off) { ta = s_dA[tid - off]; tb = s_dB[tid - off]; }
        __syncthreads();
        if (tid < 128 && tid >= off) { s_dA[tid] += ta; s_dB[tid] += tb; }
        __syncthreads();
    }
    if (tid <= 128) {
        s_uA[tid] = A0 + (tid ? s_dA[tid - 1] : 0.0f);
        s_uB[tid] = B0 + (tid ? s_dB[tid - 1] : 0.0f);
    }
    __syncthreads();
    {   // gmax over segment endpoints (identical in every block)
        float gm = -3.0e38f;
        if (tid <= 128) {
            float lo = tid ? fminf(s_ukey[tid - 1], 1.0f) : 0.0f;
            float hi = (tid < 128) ? fminf(s_ukey[tid], 1.0f) : 1.0f;
            float A = s_uA[tid], B = s_uB[tid];
            gm = fmaxf(fmaf(A, lo, B), fmaf(A, hi, B));
        }
        s_red[tid] = gm;
    }
    __syncthreads();
    for (int st = 256; st > 0; st >>= 1) {
        if (tid < st) s_red[tid] = fmaxf(s_red[tid], s_red[tid + st]);
        __syncthreads();
    }
    float gmax = s_red[0];

    // ---------- P5: packed LUT (useg<<16 | vbin) + zero bins ----------
    for (int b = tid; b < LUTN; b += NTHR) {
        float e = (float)b * (1.0f / LUTN);
        int u0 = 0;
        #pragma unroll
        for (int st = 128; st > 0; st >>= 1) {
            int c = u0 + st;
            if (c <= 128 && s_ukey[c - 1] <= e) u0 = c;
        }
        int v0 = 0;
        #pragma unroll
        for (int st = 256; st > 0; st >>= 1) {
            int c = v0 + st;
            if (c <= 256 && s_tkey[c - 1] <= e) v0 = c;
        }
        s_lut[b] = ((unsigned)u0 << 16) | (unsigned)v0;
    }
    if (tid < 257) { s_binW[tid] = 0.0f; s_binWE[tid] = 0.0f; }
    __syncthreads();

    // ---------- P6: edge pass ----------
    {
        int nq = P >> 2;
        const float4* a4 = (const float4*)adj;
        for (int q = bid * NTHR + tid; q < nq; q += NBLK * NTHR) {
            float4 v = __ldg(a4 + q);
            float es[4] = {v.x, v.y, v.z, v.w};
            #pragma unroll
            for (int j = 0; j < 4; j++) {
                float e = es[j];
                if (e > 0.0f && e < 1.0f) {
                    unsigned lv = s_lut[(int)(e * (float)LUTN)];
                    int useg = lv >> 16, vbin = lv & 0xffff;
                    while (useg < 128 && s_ukey[useg] <= e) useg++;
                    while (vbin < 256 && s_tkey[vbin] <= e) vbin++;
                    float w = __expf(fmaf(s_uA[useg], e, s_uB[useg]) - gmax);
                    atomicAdd(&s_binW[vbin], w);
                    atomicAdd(&s_binWE[vbin], w * e);
                }
            }
        }
        for (int pp = (nq << 2) + bid * NTHR + tid; pp < P; pp += NBLK * NTHR) {
            float e = __ldg(adj + pp);
            if (e > 0.0f && e < 1.0f) {
                unsigned lv = s_lut[(int)(e * (float)LUTN)];
                int useg = lv >> 16, vbin = lv & 0xffff;
                while (useg < 128 && s_ukey[useg] <= e) useg++;
                while (vbin < 256 && s_tkey[vbin] <= e) vbin++;
                float w = __expf(fmaf(s_uA[useg], e, s_uB[useg]) - gmax);
                atomicAdd(&s_binW[vbin], w);
                atomicAdd(&s_binWE[vbin], w * e);
            }
        }
    }
    __syncthreads();

    // ---------- flush bins + ticket ----------
    if (tid < 257) {
        float w = s_binW[tid], we = s_binWE[tid];
        if (w != 0.0f || we != 0.0f) {
            atomicAdd(&d_binW[tid], w);
            atomicAdd(&d_binWE[tid], we);
        }
    }
    __threadfence();
    __syncthreads();
    if (tid == 0) s_tk = atomicAdd(&g_done, 1u);
    __syncthreads();

    if (bid != 0) {
        if (bid <= 3) {   // warm L2 for block 0's head
            const float* wp = (bid == 1) ? W3b : (bid == 2) ? W4a : W4b;
            int n = (bid == 3) ? 256 * 64 : 256 * 128;
            float acc = 0.0f;
            for (int i = tid * 32; i < n; i += NTHR * 32) acc += __ldg(wp + i);
            if (acc == 1.0e38f) d_sink = acc;
        }
        return;
    }

    // ---------- block 0: wait all tickets of this run ----------
    if (tid == 0) {
        unsigned target = (s_tk / NBLK + 1u) * NBLK;
        for (;;) {
            unsigned cur;
            asm volatile("ld.volatile.global.u32 %0, [%1];" : "=r"(cur) : "l"(&g_done));
            if ((int)(cur - target) >= 0) break;
            __nanosleep(64);
        }
        __threadfence();
    }
    __syncthreads();

    // ---------- P7: prefix scans over 257 bins ----------
    if (tid < 257) { s_PF[tid] = d_binW[tid]; s_PG[tid] = d_binWE[tid]; }
    __syncthreads();
    for (int off = 1; off < 257; off <<= 1) {
        float a = 0.0f, g = 0.0f;
        if (tid < 257 && tid >= off) { a = s_PF[tid - off]; g = s_PG[tid - off]; }
        __syncthreads();
        if (tid < 257 && tid >= off) { s_PF[tid] += a; s_PG[tid] += g; }
        __syncthreads();
    }
    if (tid == 0) s_Zs = s_PF[256];
    __syncthreads();
    float Z = s_Zs, Gtot = s_PG[256];
    float invZ = (Z > 0.0f) ? (1.0f / Z) : 0.0f;
    float S0   = (Z > 0.0f) ? 1.0f : 0.0f;

    // ---------- P8: H per dim (O(1)) ----------
    if (tid < 256) {
        float r = s_r[tid], s = s_s[tid];
        int m = s_pos[tid];
        float H;
        if (r > 0.0f)      H = r * (Gtot - s_PG[m - 1]) + s * (Z - s_PF[m - 1]);
        else if (r < 0.0f) H = r * s_PG[m - 1] + s * s_PF[m - 1];
        else               H = (s > 0.0f) ? s * Z : 0.0f;
        s_Hn[tid] = H * invZ;
    }
    __syncthreads();

    // ---------- P9: head MLP ----------
    {   // weighted = Hn @ W3b + S0*b3b
        float a2 = 0.0f;
        int d0 = team * 64;
        #pragma unroll 8
        for (int d = d0; d < d0 + 64; d++)
            a2 = fmaf(s_Hn[d], __ldg(W3b + d * 128 + col), a2);
        s_pa[team][col] = a2;
    }
    __syncthreads();
    if (tid < 128)
        s_Wt[tid] = s_pa[0][tid] + s_pa[1][tid] + s_pa[2][tid] + s_pa[3][tid] + S0 * __ldg(b3b + tid);
    __syncthreads();
    {   // h4 = relu(weighted @ W4a + b4a)
        float a3 = 0.0f;
        int m0 = team2 * 64;
        #pragma unroll 8
        for (int m = m0; m < m0 + 64; m++)
            a3 = fmaf(s_Wt[m], __ldg(W4a + m * 256 + col2), a3);
        s_pr[team2][col2] = a3;
    }
    __syncthreads();
    if (tid < 256) s_H4[tid] = fmaxf(s_pr[0][tid] + s_pr[1][tid] + __ldg(b4a + tid), 0.0f);
    __syncthreads();
    {   // out = h4 @ W4b + b4b
        int colO = tid & 63, team3 = tid >> 6;
        float a4 = 0.0f;
        int n0_ = team3 * 32;
        #pragma unroll 8
        for (int n = n0_; n < n0_ + 32; n++)
            a4 = fmaf(s_H4[n], __ldg(W4b + n * 64 + colO), a4);
        s_red[tid] = a4;
    }
    __syncthreads();
    if (tid < 64) {
        float o = __ldg(b4b + tid);
        #pragma unroll
        for (int q = 0; q < 8; q++) o += s_red[q * 64 + tid];
        out[tid] = o;
    }
    // reset global bins for next replay
    if (tid < 257) { d_binW[tid] = 0.0f; d_binWE[tid] = 0.0f; }
}

// ---------------- launch: ONE kernel, one graph node ----------------
extern "C" void kernel_launch(void* const* d_in, const int* in_sizes, int n_in,
                              void* d_out, int out_size) {
    const float* adj = (const float*)d_in[1];
    int P = in_sizes[1];
    k_fused<<<NBLK, NTHR>>>(adj, P,
        (const float*)d_in[3],  (const float*)d_in[4],
        (const float*)d_in[5],  (const float*)d_in[6],
        (const float*)d_in[7],  (const float*)d_in[8],
        (const float*)d_in[9],  (const float*)d_in[10],
        (const float*)d_in[11], (const float*)d_in[12],
        (const float*)d_in[13], (const float*)d_in[14],
        (const float*)d_in[15], (const float*)d_in[16],
        (const float*)d_in[17], (const float*)d_in[18],
        (float*)d_out);
}